// round 2
// baseline (speedup 1.0000x reference)
#include <cuda_runtime.h>

#define NB 64
#define ND 512
#define NH 32
#define NW 32
#define NK 64
#define NN 1024   // NH*NW

// Scratch (device globals: no allocations allowed)
__device__ float g_feat[NB*NK*NN];   // 16 MB; holds features, then softmax a in-place
__device__ float g_V[NB*NK*ND];      // 8 MB; V[b,k,d]
__device__ float g_inv[NB*ND];       // 1/max(||V[., :, .]||, eps) per (b,d)

// ---------------------------------------------------------------------------
// GEMM1: feat[b,k,n] = sum_d w[k,d] * x[b,d,n]
// Block tile: 64(K) x 64(N), reduction chunk 16 over D. 256 threads, 4x4 micro.
// ---------------------------------------------------------------------------
__global__ __launch_bounds__(256, 2) void k_gemm1(const float* __restrict__ x,
                                                  const float* __restrict__ w) {
    __shared__ float sW[16][68];  // [d_local][k], padded, 16B-aligned rows
    __shared__ float sX[16][64];  // [d_local][n]
    const int b   = blockIdx.y;
    const int n0  = blockIdx.x * 64;
    const int tid = threadIdx.x;
    const int tx  = tid & 15;     // n micro group
    const int ty  = tid >> 4;     // k micro group
    const int ld_d  = tid & 15;
    const int ld_k0 = tid >> 4;   // 0..15
    const int ld_n  = tid & 63;
    const int ld_dd = tid >> 6;   // 0..3

    float acc[4][4] = {};

    for (int d0 = 0; d0 < ND; d0 += 16) {
        #pragma unroll
        for (int i = 0; i < 4; i++) {
            int kk = ld_k0 + i * 16;
            sW[ld_d][kk] = w[kk * ND + d0 + ld_d];
        }
        #pragma unroll
        for (int i = 0; i < 4; i++) {
            int dd = ld_dd + i * 4;
            sX[dd][ld_n] = x[(b * ND + d0 + dd) * NN + n0 + ld_n];
        }
        __syncthreads();
        #pragma unroll
        for (int dd = 0; dd < 16; dd++) {
            float4 rw = *(const float4*)&sW[dd][ty * 4];
            float4 rx = *(const float4*)&sX[dd][tx * 4];
            float aW[4] = {rw.x, rw.y, rw.z, rw.w};
            float aX[4] = {rx.x, rx.y, rx.z, rx.w};
            #pragma unroll
            for (int i = 0; i < 4; i++)
                #pragma unroll
                for (int j = 0; j < 4; j++)
                    acc[i][j] = fmaf(aW[i], aX[j], acc[i][j]);
        }
        __syncthreads();
    }
    #pragma unroll
    for (int i = 0; i < 4; i++) {
        int k = ty * 4 + i;
        float4 v = make_float4(acc[i][0], acc[i][1], acc[i][2], acc[i][3]);
        *(float4*)&g_feat[(b * NK + k) * NN + n0 + tx * 4] = v;
    }
}

// ---------------------------------------------------------------------------
// Softmax over H (axis=2) only: for each (b,k,w) column of 32 values, stride NW.
// One 32-thread block per (b,k); thread t owns column w=t.
// ---------------------------------------------------------------------------
__global__ void k_softmax() {
    const int bk = blockIdx.x;
    const int t  = threadIdx.x;  // 0..31 = w index
    float* p = g_feat + bk * NN + t;
    float v[NH];
    float m = -1e30f;
    #pragma unroll
    for (int h = 0; h < NH; h++) { v[h] = p[h * NW]; m = fmaxf(m, v[h]); }
    float s = 0.f;
    #pragma unroll
    for (int h = 0; h < NH; h++) { v[h] = __expf(v[h] - m); s += v[h]; }
    const float inv = 1.f / s;
    #pragma unroll
    for (int h = 0; h < NH; h++) p[h * NW] = v[h] * inv;
}

// ---------------------------------------------------------------------------
// GEMM2: V[b,k,d] = sum_n a[b,k,n] * x[b,d,n]  -  32 * c[k,d]
// (a.sum over n is exactly 32: each of the W softmax columns sums to 1.)
// Block tile: 64(K) x 64(D), reduction chunk 32 over N. 256 threads, 4x4 micro.
// ---------------------------------------------------------------------------
__global__ __launch_bounds__(256, 2) void k_gemm2(const float* __restrict__ x,
                                                  const float* __restrict__ c) {
    __shared__ float sA[32][68];  // [n_local][k]
    __shared__ float sX[32][68];  // [n_local][d]
    const int b   = blockIdx.y;
    const int d0  = blockIdx.x * 64;
    const int tid = threadIdx.x;
    const int tx  = tid & 15;     // d micro group
    const int ty  = tid >> 4;     // k micro group
    const int ld_n = tid & 31;
    const int ld_r = tid >> 5;    // 0..7

    float acc[4][4] = {};
    const float* aBase = g_feat + b * NK * NN;
    const float* xBase = x + (b * ND + d0) * NN;

    for (int n0 = 0; n0 < NN; n0 += 32) {
        #pragma unroll
        for (int i = 0; i < 8; i++) {
            int kk = ld_r + i * 8;
            sA[ld_n][kk] = aBase[kk * NN + n0 + ld_n];
        }
        #pragma unroll
        for (int i = 0; i < 8; i++) {
            int dd = ld_r + i * 8;
            sX[ld_n][dd] = xBase[dd * NN + n0 + ld_n];
        }
        __syncthreads();
        #pragma unroll
        for (int nn = 0; nn < 32; nn++) {
            float4 ra = *(const float4*)&sA[nn][ty * 4];
            float4 rx = *(const float4*)&sX[nn][tx * 4];
            float aA[4] = {ra.x, ra.y, ra.z, ra.w};
            float aX[4] = {rx.x, rx.y, rx.z, rx.w};
            #pragma unroll
            for (int i = 0; i < 4; i++)
                #pragma unroll
                for (int j = 0; j < 4; j++)
                    acc[i][j] = fmaf(aA[i], aX[j], acc[i][j]);
        }
        __syncthreads();
    }
    #pragma unroll
    for (int i = 0; i < 4; i++) {
        int k = ty * 4 + i;
        float4 cc = *(const float4*)&c[k * ND + d0 + tx * 4];
        float4 o;
        o.x = acc[i][0] - 32.0f * cc.x;
        o.y = acc[i][1] - 32.0f * cc.y;
        o.z = acc[i][2] - 32.0f * cc.z;
        o.w = acc[i][3] - 32.0f * cc.w;
        *(float4*)&g_V[(b * NK + k) * ND + d0 + tx * 4] = o;
    }
}

// ---------------------------------------------------------------------------
// Norms over K for each (b,d): inv = 1/max(||V||_2, 1e-12)
// ---------------------------------------------------------------------------
__global__ void k_norm() {
    const int b = blockIdx.x;
    const int d = blockIdx.y * 256 + threadIdx.x;
    float ss = 0.f;
    #pragma unroll 8
    for (int k = 0; k < NK; k++) {
        float v = g_V[(b * NK + k) * ND + d];
        ss = fmaf(v, v, ss);
    }
    g_inv[b * ND + d] = 1.f / fmaxf(sqrtf(ss), 1e-12f);
}

// ---------------------------------------------------------------------------
// Scale + transpose (b,k,d) -> out (d,k,b). 32x32 smem tiles per k.
// Second F.normalize is idempotent on a unit vector -> applied once.
// ---------------------------------------------------------------------------
__global__ void k_transpose(float* __restrict__ out) {
    __shared__ float tile[32][33];
    const int k  = blockIdx.z;
    const int d0 = blockIdx.x * 32;
    const int b0 = blockIdx.y * 32;
    const int tx = threadIdx.x;   // 32
    const int ty = threadIdx.y;   // 8
    #pragma unroll
    for (int i = 0; i < 4; i++) {
        int bb = b0 + ty + i * 8;
        tile[ty + i * 8][tx] = g_V[(bb * NK + k) * ND + d0 + tx] *
                               g_inv[bb * ND + d0 + tx];
    }
    __syncthreads();
    #pragma unroll
    for (int i = 0; i < 4; i++) {
        int dd = d0 + ty + i * 8;
        out[(dd * NK + k) * NB + b0 + tx] = tile[tx][ty + i * 8];
    }
}

extern "C" void kernel_launch(void* const* d_in, const int* in_sizes, int n_in,
                              void* d_out, int out_size) {
    const float* x = (const float*)d_in[0];  // (B,D,H,W)
    const float* w = (const float*)d_in[1];  // (K,D)
    const float* c = (const float*)d_in[2];  // (K,D)
    float* out = (float*)d_out;              // (D,K,B)

    k_gemm1<<<dim3(16, 64), 256>>>(x, w);
    k_softmax<<<NB * NK, 32>>>();
    k_gemm2<<<dim3(8, 64), 256>>>(x, c);
    k_norm<<<dim3(64, 2), 256>>>();
    k_transpose<<<dim3(16, 2, 64), dim3(32, 8)>>>(out);
}

// round 4
// speedup vs baseline: 2.9355x; 2.9355x over previous
#include <cuda_runtime.h>
#include <cstdint>

#define NB 64
#define ND 512
#define NK 64
#define NN 1024   // H*W

// scratch: features, then softmax a in-place (fp32)
__device__ float g_feat[(size_t)NB * NK * NN];   // 16 MB

__device__ __forceinline__ uint32_t f2tf32(float f) {
    uint32_t r;
    asm("cvt.rna.tf32.f32 %0, %1;" : "=r"(r) : "f"(f));
    return r;
}

__device__ __forceinline__ void mma8(float* c, const uint32_t* a, const uint32_t* b) {
    asm volatile(
        "mma.sync.aligned.m16n8k8.row.col.f32.tf32.tf32.f32 "
        "{%0,%1,%2,%3}, {%4,%5,%6,%7}, {%8,%9}, {%0,%1,%2,%3};"
        : "+f"(c[0]), "+f"(c[1]), "+f"(c[2]), "+f"(c[3])
        : "r"(a[0]), "r"(a[1]), "r"(a[2]), "r"(a[3]), "r"(b[0]), "r"(b[1]));
}

// ---------------------------------------------------------------------------
// GEMM1: feat[b,kcl,n] = sum_d w[kcl,d] * x[b,d,n]
// CTA: M=128(n) x N=64(kcl), K=512(d) in chunks of 32. 8 warps (4m x 2n),
// warp tile 32x32 = 2x4 mma(m16n8k8). tf32 single pass.
// ---------------------------------------------------------------------------
#define XS1 136   // [32 d][128 n] padded stride (conflict-free frag loads)
#define WS1 36    // [64 kcl][32 d]
__global__ __launch_bounds__(256, 2) void k_gemm1(const float* __restrict__ x,
                                                  const float* __restrict__ w) {
    __shared__ float xs[32 * XS1];
    __shared__ float ws[64 * WS1];
    const int b = blockIdx.y, n0 = blockIdx.x * 128;
    const int tid = threadIdx.x, lane = tid & 31, wid = tid >> 5;
    const int wm = (wid & 3) * 32;    // n-dim (M) offset
    const int wn = (wid >> 2) * 32;   // kcl (N) offset
    const int q = lane >> 2, r = lane & 3;

    const int xr = tid >> 3, xc0 = (tid & 7) * 16;
    const int wr = tid >> 2, wc0 = (tid & 3) * 8;

    float acc[2][4][4] = {};

    for (int d0 = 0; d0 < ND; d0 += 32) {
        const float* xg = x + ((size_t)(b * ND + d0 + xr)) * NN + n0 + xc0;
        #pragma unroll
        for (int i = 0; i < 4; i++)
            *(float4*)&xs[xr * XS1 + xc0 + i * 4] = *(const float4*)(xg + i * 4);
        const float* wg = w + (size_t)wr * ND + d0 + wc0;
        #pragma unroll
        for (int i = 0; i < 2; i++)
            *(float4*)&ws[wr * WS1 + wc0 + i * 4] = *(const float4*)(wg + i * 4);
        __syncthreads();

        #pragma unroll
        for (int kk = 0; kk < 32; kk += 8) {
            uint32_t af[2][4], bf[4][2];
            #pragma unroll
            for (int mt = 0; mt < 2; mt++) {
                int m = wm + mt * 16 + q;
                af[mt][0] = f2tf32(xs[(kk + r) * XS1 + m]);
                af[mt][1] = f2tf32(xs[(kk + r) * XS1 + m + 8]);
                af[mt][2] = f2tf32(xs[(kk + r + 4) * XS1 + m]);
                af[mt][3] = f2tf32(xs[(kk + r + 4) * XS1 + m + 8]);
            }
            #pragma unroll
            for (int nt = 0; nt < 4; nt++) {
                int n = wn + nt * 8 + q;
                bf[nt][0] = f2tf32(ws[n * WS1 + kk + r]);
                bf[nt][1] = f2tf32(ws[n * WS1 + kk + r + 4]);
            }
            #pragma unroll
            for (int mt = 0; mt < 2; mt++)
                #pragma unroll
                for (int nt = 0; nt < 4; nt++)
                    mma8(acc[mt][nt], af[mt], bf[nt]);
        }
        __syncthreads();
    }

    float* fb = g_feat + (size_t)b * NK * NN + n0;
    #pragma unroll
    for (int mt = 0; mt < 2; mt++) {
        int m = wm + mt * 16 + q;
        #pragma unroll
        for (int nt = 0; nt < 4; nt++) {
            int kcl = wn + nt * 8 + 2 * r;
            fb[(size_t)kcl * NN + m]           = acc[mt][nt][0];
            fb[(size_t)(kcl + 1) * NN + m]     = acc[mt][nt][1];
            fb[(size_t)kcl * NN + m + 8]       = acc[mt][nt][2];
            fb[(size_t)(kcl + 1) * NN + m + 8] = acc[mt][nt][3];
        }
    }
}

// ---------------------------------------------------------------------------
// Softmax over H only: per (b,k,w) column of 32 values at stride 32. In-place.
// ---------------------------------------------------------------------------
__global__ void k_softmax() {
    const int bk = blockIdx.x * 8 + (threadIdx.x >> 5);
    const int t = threadIdx.x & 31;
    float* p = g_feat + (size_t)bk * NN + t;
    float v[32];
    float m = -1e30f;
    #pragma unroll
    for (int h = 0; h < 32; h++) { v[h] = p[h * 32]; m = fmaxf(m, v[h]); }
    float s = 0.f;
    #pragma unroll
    for (int h = 0; h < 32; h++) { v[h] = __expf(v[h] - m); s += v[h]; }
    const float inv = 1.f / s;
    #pragma unroll
    for (int h = 0; h < 32; h++) p[h * 32] = v[h] * inv;
}

// ---------------------------------------------------------------------------
// GEMM2: V[b,kcl,d] = sum_n a[b,kcl,n] x[b,d,n] - 32*c[kcl,d]
// CTA: M=128(d) x N=64(kcl), K=1024(n) in chunks of 32.
// Fused epilogue: -32c, L2-normalize over kcl per (d,b), write out[d,kcl,b].
// (sum_n a == 32 exactly: each softmax column sums to 1, W=32 columns.)
// ---------------------------------------------------------------------------
#define XS2 36   // [128 d][32 n]
#define AS2 36   // [64 kcl][32 n]
#define VS2 68   // [128 d][64 kcl] epilogue staging
__global__ __launch_bounds__(256, 2) void k_gemm2(const float* __restrict__ x,
                                                  const float* __restrict__ cc,
                                                  float* __restrict__ out) {
    __shared__ __align__(16) char sm[128 * VS2 * 4];  // 34816 B (>= 18432+9216)
    float* xs = (float*)sm;               // [128][XS2]
    float* as = (float*)(sm + 128 * XS2 * 4);  // [64][AS2]
    float* Vs = (float*)sm;               // [128][VS2] (after mma loop)

    const int b = blockIdx.y, d0 = blockIdx.x * 128;
    const int tid = threadIdx.x, lane = tid & 31, wid = tid >> 5;
    const int wm = (wid & 3) * 32;    // d (M) offset
    const int wn = (wid >> 2) * 32;   // kcl (N) offset
    const int q = lane >> 2, r = lane & 3;

    const int xr = tid >> 1, xc0 = (tid & 1) * 16;
    const int ar = tid >> 2, ac0 = (tid & 3) * 8;

    float acc[2][4][4] = {};

    for (int n0 = 0; n0 < NN; n0 += 32) {
        const float* xg = x + ((size_t)(b * ND + d0 + xr)) * NN + n0 + xc0;
        #pragma unroll
        for (int i = 0; i < 4; i++)
            *(float4*)&xs[xr * XS2 + xc0 + i * 4] = *(const float4*)(xg + i * 4);
        const float* ag = g_feat + ((size_t)(b * NK + ar)) * NN + n0 + ac0;
        #pragma unroll
        for (int i = 0; i < 2; i++)
            *(float4*)&as[ar * AS2 + ac0 + i * 4] = *(const float4*)(ag + i * 4);
        __syncthreads();

        #pragma unroll
        for (int kk = 0; kk < 32; kk += 8) {
            uint32_t af[2][4], bf[4][2];
            #pragma unroll
            for (int mt = 0; mt < 2; mt++) {
                int m = wm + mt * 16 + q;
                af[mt][0] = f2tf32(xs[m * XS2 + kk + r]);
                af[mt][1] = f2tf32(xs[(m + 8) * XS2 + kk + r]);
                af[mt][2] = f2tf32(xs[m * XS2 + kk + r + 4]);
                af[mt][3] = f2tf32(xs[(m + 8) * XS2 + kk + r + 4]);
            }
            #pragma unroll
            for (int nt = 0; nt < 4; nt++) {
                int n = wn + nt * 8 + q;
                bf[nt][0] = f2tf32(as[n * AS2 + kk + r]);
                bf[nt][1] = f2tf32(as[n * AS2 + kk + r + 4]);
            }
            #pragma unroll
            for (int mt = 0; mt < 2; mt++)
                #pragma unroll
                for (int nt = 0; nt < 4; nt++)
                    mma8(acc[mt][nt], af[mt], bf[nt]);
        }
        __syncthreads();
    }

    // stage raw V (pre -32c) into smem
    #pragma unroll
    for (int mt = 0; mt < 2; mt++) {
        int m = wm + mt * 16 + q;
        #pragma unroll
        for (int nt = 0; nt < 4; nt++) {
            int kcl = wn + nt * 8 + 2 * r;
            Vs[m * VS2 + kcl]           = acc[mt][nt][0];
            Vs[m * VS2 + kcl + 1]       = acc[mt][nt][1];
            Vs[(m + 8) * VS2 + kcl]     = acc[mt][nt][2];
            Vs[(m + 8) * VS2 + kcl + 1] = acc[mt][nt][3];
        }
    }
    __syncthreads();

    // norm over kcl per d, then transposed store out[(d)*K*B + k*B + b]
    if (tid < 128) {
        const float* crow = cc + d0 + tid;      // c[k*ND + d0+tid], coalesced over tid
        float ss = 0.f;
        #pragma unroll
        for (int k = 0; k < NK; k++) {
            float v = Vs[tid * VS2 + k] - 32.0f * crow[(size_t)k * ND];
            ss = fmaf(v, v, ss);
        }
        const float inv = 1.f / fmaxf(sqrtf(ss), 1e-12f);
        float* op = out + (size_t)(d0 + tid) * NK * NB + b;
        #pragma unroll
        for (int k = 0; k < NK; k++) {
            float v = Vs[tid * VS2 + k] - 32.0f * crow[(size_t)k * ND];
            op[(size_t)k * NB] = v * inv;
        }
    }
}

// ---------------------------------------------------------------------------
extern "C" void kernel_launch(void* const* d_in, const int* in_sizes, int n_in,
                              void* d_out, int out_size) {
    const float* x = (const float*)d_in[0];  // (B,D,H,W)
    const float* w = (const float*)d_in[1];  // (K,D)
    const float* c = (const float*)d_in[2];  // (K,D)
    float* out = (float*)d_out;              // (D,K,B)

    k_gemm1<<<dim3(NN / 128, NB), 256>>>(x, w);
    k_softmax<<<NB * NK / 8, 256>>>();
    k_gemm2<<<dim3(ND / 128, NB), 256>>>(x, c, out);
}

// round 5
// speedup vs baseline: 4.8831x; 1.6634x over previous
#include <cuda_runtime.h>
#include <cstdint>

#define NB 64
#define ND 512
#define NK 64
#define NN 1024   // H*W

__device__ float g_feat[(size_t)NB * NK * NN];   // 16 MB: features, then a in-place

__device__ __forceinline__ uint32_t f2tf32(float f) {
    uint32_t r;
    asm("cvt.rna.tf32.f32 %0, %1;" : "=r"(r) : "f"(f));
    return r;
}
__device__ __forceinline__ uint32_t smem_u32(const void* p) {
    uint32_t a;
    asm("{ .reg .u64 t; cvta.to.shared.u64 t, %1; cvt.u32.u64 %0, t; }" : "=r"(a) : "l"(p));
    return a;
}
__device__ __forceinline__ void mma8(float* c, const uint32_t* a, const uint32_t* b) {
    asm volatile(
        "mma.sync.aligned.m16n8k8.row.col.f32.tf32.tf32.f32 "
        "{%0,%1,%2,%3}, {%4,%5,%6,%7}, {%8,%9}, {%0,%1,%2,%3};"
        : "+f"(c[0]), "+f"(c[1]), "+f"(c[2]), "+f"(c[3])
        : "r"(a[0]), "r"(a[1]), "r"(a[2]), "r"(a[3]), "r"(b[0]), "r"(b[1]));
}
#define CPA16(dst, src) \
    asm volatile("cp.async.cg.shared.global [%0], [%1], 16;" :: "r"(dst), "l"(src))
#define CPA_COMMIT() asm volatile("cp.async.commit_group;" ::: "memory")
#define CPA_WAIT1()  asm volatile("cp.async.wait_group 1;" ::: "memory")
#define CPA_WAIT0()  asm volatile("cp.async.wait_group 0;" ::: "memory")

// ---------------------------------------------------------------------------
// GEMM1: feat[b,kcl,n] = sum_d w[kcl,d] * x[b,d,n]
// CTA 128(n=M) x 64(kcl=N), K=512 in 16 chunks of 32. 128 thr, 4 warps
// (2m x 2n), warp tile 64x32 (mt=4, nt=4). cp.async double-buffered.
// smem: xs[2][32][136] (A: [d][n]), ws[2][64][36] (B: [kcl][d])
// ---------------------------------------------------------------------------
#define XS1 136
#define WS1 36
#define G1_XS (32 * XS1)
#define G1_WS (64 * WS1)
#define G1_SMEM ((2 * G1_XS + 2 * G1_WS) * 4)

__global__ __launch_bounds__(128) void k_gemm1(const float* __restrict__ x,
                                               const float* __restrict__ w) {
    extern __shared__ __align__(16) float sm[];
    float* xs = sm;
    float* ws = sm + 2 * G1_XS;
    const uint32_t xs_u = smem_u32(xs), ws_u = smem_u32(ws);

    const int b = blockIdx.y, n0 = blockIdx.x * 128;
    const int t = threadIdx.x, lane = t & 31, wid = t >> 5;
    const int wm = (wid & 1) * 64, wn = (wid >> 1) * 32;
    const int q = lane >> 2, r = lane & 3;

    const int xrow = t >> 5, xcol = t & 31;          // xs: 8 iters, rows +4
    const int wrow = t >> 3, wcol = t & 7;           // ws: 4 iters, rows +16

    float acc[4][4][4] = {};

    // ---- loader ----
    auto load_chunk = [&](int ch, int bi) {
        const int d0 = ch * 32;
        uint32_t xd = xs_u + bi * G1_XS * 4;
        const float* xg = x + ((size_t)(b * ND + d0 + xrow)) * NN + n0 + xcol * 4;
        #pragma unroll
        for (int i = 0; i < 8; i++)
            CPA16(xd + (xrow + i * 4) * (XS1 * 4) + xcol * 16,
                  xg + (size_t)i * 4 * NN);
        uint32_t wd = ws_u + bi * G1_WS * 4;
        const float* wg = w + (size_t)wrow * ND + d0 + wcol * 4;
        #pragma unroll
        for (int i = 0; i < 4; i++)
            CPA16(wd + (wrow + i * 16) * (WS1 * 4) + wcol * 16,
                  wg + (size_t)i * 16 * ND);
        CPA_COMMIT();
    };

    load_chunk(0, 0);
    for (int ch = 0; ch < 16; ch++) {
        if (ch + 1 < 16) { load_chunk(ch + 1, (ch + 1) & 1); CPA_WAIT1(); }
        else CPA_WAIT0();
        __syncthreads();
        const float* xc = xs + (ch & 1) * G1_XS;
        const float* wc = ws + (ch & 1) * G1_WS;
        #pragma unroll
        for (int kk = 0; kk < 32; kk += 8) {
            uint32_t af[4][4], bf[4][2];
            #pragma unroll
            for (int mt = 0; mt < 4; mt++) {
                int m = wm + mt * 16 + q;
                af[mt][0] = f2tf32(xc[(kk + r) * XS1 + m]);
                af[mt][1] = f2tf32(xc[(kk + r) * XS1 + m + 8]);
                af[mt][2] = f2tf32(xc[(kk + r + 4) * XS1 + m]);
                af[mt][3] = f2tf32(xc[(kk + r + 4) * XS1 + m + 8]);
            }
            #pragma unroll
            for (int nt = 0; nt < 4; nt++) {
                int n = wn + nt * 8 + q;
                bf[nt][0] = f2tf32(wc[n * WS1 + kk + r]);
                bf[nt][1] = f2tf32(wc[n * WS1 + kk + r + 4]);
            }
            #pragma unroll
            for (int mt = 0; mt < 4; mt++)
                #pragma unroll
                for (int nt = 0; nt < 4; nt++)
                    mma8(acc[mt][nt], af[mt], bf[nt]);
        }
        __syncthreads();
    }

    float* fb = g_feat + (size_t)b * NK * NN + n0;
    #pragma unroll
    for (int mt = 0; mt < 4; mt++) {
        int m = wm + mt * 16 + q;
        #pragma unroll
        for (int nt = 0; nt < 4; nt++) {
            int kcl = wn + nt * 8 + 2 * r;
            fb[(size_t)kcl * NN + m]           = acc[mt][nt][0];
            fb[(size_t)(kcl + 1) * NN + m]     = acc[mt][nt][1];
            fb[(size_t)kcl * NN + m + 8]       = acc[mt][nt][2];
            fb[(size_t)(kcl + 1) * NN + m + 8] = acc[mt][nt][3];
        }
    }
}

// ---------------------------------------------------------------------------
// Softmax over H only: per (b,k,w) column of 32 values at stride 32. In-place.
// ---------------------------------------------------------------------------
__global__ void k_softmax() {
    const int bk = blockIdx.x * 8 + (threadIdx.x >> 5);
    const int t = threadIdx.x & 31;
    float* p = g_feat + (size_t)bk * NN + t;
    float v[32];
    float m = -1e30f;
    #pragma unroll
    for (int h = 0; h < 32; h++) { v[h] = p[h * 32]; m = fmaxf(m, v[h]); }
    float s = 0.f;
    #pragma unroll
    for (int h = 0; h < 32; h++) { v[h] = __expf(v[h] - m); s += v[h]; }
    const float inv = 1.f / s;
    #pragma unroll
    for (int h = 0; h < 32; h++) p[h * 32] = v[h] * inv;
}

// ---------------------------------------------------------------------------
// GEMM2: V[b,kcl,d] = sum_n a[b,kcl,n] x[b,d,n] - 32*c[kcl,d]
// CTA 128(d=M) x 64(kcl=N), K=1024 in 32 chunks of 32. Same warp layout.
// Fused epilogue: -32c, L2-normalize over kcl per (d,b), store out[d,kcl,b].
// (sum_n a == 32 exactly: softmax columns each sum to 1, W=32 of them.)
// smem: xs[2][128][36] (A: [d][n]), as[2][64][36] (B: [kcl][n])
// ---------------------------------------------------------------------------
#define XS2 36
#define AS2 36
#define G2_XS (128 * XS2)
#define G2_AS (64 * AS2)
#define G2_SMEM ((2 * G2_XS + 2 * G2_AS) * 4)
#define VS2 65

__global__ __launch_bounds__(128) void k_gemm2(const float* __restrict__ x,
                                               const float* __restrict__ cc,
                                               float* __restrict__ out) {
    extern __shared__ __align__(16) float sm[];
    float* xs = sm;
    float* as = sm + 2 * G2_XS;
    const uint32_t xs_u = smem_u32(xs), as_u = smem_u32(as);

    const int b = blockIdx.y, d0 = blockIdx.x * 128;
    const int t = threadIdx.x, lane = t & 31, wid = t >> 5;
    const int wm = (wid & 1) * 64, wn = (wid >> 1) * 32;
    const int q = lane >> 2, r = lane & 3;

    const int xrow = t >> 3, xcol = t & 7;

    float acc[4][4][4] = {};

    auto load_chunk = [&](int ch, int bi) {
        const int n0 = ch * 32;
        uint32_t xd = xs_u + bi * G2_XS * 4;
        const float* xg = x + ((size_t)(b * ND + d0 + xrow)) * NN + n0 + xcol * 4;
        #pragma unroll
        for (int i = 0; i < 8; i++)
            CPA16(xd + (xrow + i * 16) * (XS2 * 4) + xcol * 16,
                  xg + (size_t)i * 16 * NN);
        uint32_t ad = as_u + bi * G2_AS * 4;
        const float* ag = g_feat + ((size_t)(b * NK + xrow)) * NN + n0 + xcol * 4;
        #pragma unroll
        for (int i = 0; i < 4; i++)
            CPA16(ad + (xrow + i * 16) * (AS2 * 4) + xcol * 16,
                  ag + (size_t)i * 16 * NN);
        CPA_COMMIT();
    };

    load_chunk(0, 0);
    for (int ch = 0; ch < 32; ch++) {
        if (ch + 1 < 32) { load_chunk(ch + 1, (ch + 1) & 1); CPA_WAIT1(); }
        else CPA_WAIT0();
        __syncthreads();
        const float* xc = xs + (ch & 1) * G2_XS;
        const float* ac = as + (ch & 1) * G2_AS;
        #pragma unroll
        for (int kk = 0; kk < 32; kk += 8) {
            uint32_t af[4][4], bf[4][2];
            #pragma unroll
            for (int mt = 0; mt < 4; mt++) {
                int m = wm + mt * 16 + q;
                af[mt][0] = f2tf32(xc[m * XS2 + kk + r]);
                af[mt][1] = f2tf32(xc[(m + 8) * XS2 + kk + r]);
                af[mt][2] = f2tf32(xc[m * XS2 + kk + r + 4]);
                af[mt][3] = f2tf32(xc[(m + 8) * XS2 + kk + r + 4]);
            }
            #pragma unroll
            for (int nt = 0; nt < 4; nt++) {
                int n = wn + nt * 8 + q;
                bf[nt][0] = f2tf32(ac[n * AS2 + kk + r]);
                bf[nt][1] = f2tf32(ac[n * AS2 + kk + r + 4]);
            }
            #pragma unroll
            for (int mt = 0; mt < 4; mt++)
                #pragma unroll
                for (int nt = 0; nt < 4; nt++)
                    mma8(acc[mt][nt], af[mt], bf[nt]);
        }
        __syncthreads();
    }

    // stage raw V into smem (reuse xs region), stride 65 (conflict-free col reads)
    float* Vs = sm;
    #pragma unroll
    for (int mt = 0; mt < 4; mt++) {
        int m = wm + mt * 16 + q;
        #pragma unroll
        for (int nt = 0; nt < 4; nt++) {
            int kcl = wn + nt * 8 + 2 * r;
            Vs[m * VS2 + kcl]           = acc[mt][nt][0];
            Vs[m * VS2 + kcl + 1]       = acc[mt][nt][1];
            Vs[(m + 8) * VS2 + kcl]     = acc[mt][nt][2];
            Vs[(m + 8) * VS2 + kcl + 1] = acc[mt][nt][3];
        }
    }
    __syncthreads();

    // per d: subtract 32c, L2-normalize over kcl, transposed store out[d,k,b]
    const float* crow = cc + d0 + t;    // c[k*ND + d0+t], coalesced over t
    float ss = 0.f;
    #pragma unroll
    for (int k = 0; k < NK; k++) {
        float v = Vs[t * VS2 + k] - 32.0f * crow[(size_t)k * ND];
        ss = fmaf(v, v, ss);
    }
    const float inv = 1.f / fmaxf(sqrtf(ss), 1e-12f);
    float* op = out + (size_t)(d0 + t) * NK * NB + b;
    #pragma unroll
    for (int k = 0; k < NK; k++) {
        float v = Vs[t * VS2 + k] - 32.0f * crow[(size_t)k * ND];
        op[(size_t)k * NB] = v * inv;
    }
}

// ---------------------------------------------------------------------------
extern "C" void kernel_launch(void* const* d_in, const int* in_sizes, int n_in,
                              void* d_out, int out_size) {
    const float* x = (const float*)d_in[0];  // (B,D,H,W)
    const float* w = (const float*)d_in[1];  // (K,D)
    const float* c = (const float*)d_in[2];  // (K,D)
    float* out = (float*)d_out;              // (D,K,B)

    static bool attr_done = false;
    if (!attr_done) {
        cudaFuncSetAttribute(k_gemm1, cudaFuncAttributeMaxDynamicSharedMemorySize, G1_SMEM);
        cudaFuncSetAttribute(k_gemm2, cudaFuncAttributeMaxDynamicSharedMemorySize, G2_SMEM);
        attr_done = true;
    }

    k_gemm1<<<dim3(NN / 128, NB), 128, G1_SMEM>>>(x, w);
    k_softmax<<<NB * NK / 8, 256>>>();
    k_gemm2<<<dim3(ND / 128, NB), 128, G2_SMEM>>>(x, c, out);
}

// round 9
// speedup vs baseline: 5.4340x; 1.1128x over previous
#include <cuda_runtime.h>
#include <cstdint>

#define NB 64
#define ND 512
#define NK 64
#define NN 1024   // H*W

__device__ float g_feat[(size_t)NB * NK * NN];   // 16 MB: features, then a in-place
__device__ float g_V[(size_t)NB * ND * NK];      // 8 MB: normalized V, [b][d][k]

__device__ __forceinline__ uint32_t smem_u32(const void* p) {
    uint32_t a;
    asm("{ .reg .u64 t; cvta.to.shared.u64 t, %1; cvt.u32.u64 %0, t; }" : "=r"(a) : "l"(p));
    return a;
}
// tf32 mma, raw fp32 bits as operands (HW truncates mantissa; RZ vs RNA only)
__device__ __forceinline__ void mma8(float* c, const uint32_t* a, const uint32_t* b) {
    asm volatile(
        "mma.sync.aligned.m16n8k8.row.col.f32.tf32.tf32.f32 "
        "{%0,%1,%2,%3}, {%4,%5,%6,%7}, {%8,%9}, {%0,%1,%2,%3};"
        : "+f"(c[0]), "+f"(c[1]), "+f"(c[2]), "+f"(c[3])
        : "r"(a[0]), "r"(a[1]), "r"(a[2]), "r"(a[3]), "r"(b[0]), "r"(b[1]));
}
#define F2U __float_as_uint
#define CPA16(dst, src) \
    asm volatile("cp.async.cg.shared.global [%0], [%1], 16;" :: "r"(dst), "l"(src))
#define CPA_COMMIT() asm volatile("cp.async.commit_group;" ::: "memory")
#define CPA_WAIT1()  asm volatile("cp.async.wait_group 1;" ::: "memory")
#define CPA_WAIT0()  asm volatile("cp.async.wait_group 0;" ::: "memory")

// ---------------------------------------------------------------------------
// GEMM1: feat[b,kcl,n] = sum_d w[kcl,d] * x[b,d,n]
// CTA 128(n=M) x 64(kcl=N), K=512 in 16 chunks of 32. 4 warps (2m x 2n),
// warp tile 64x32. cp.async double-buffered.
// ---------------------------------------------------------------------------
#define XS1 136
#define WS1 36
#define G1_XS (32 * XS1)
#define G1_WS (64 * WS1)
#define G1_SMEM ((2 * G1_XS + 2 * G1_WS) * 4)

__global__ __launch_bounds__(128) void k_gemm1(const float* __restrict__ x,
                                               const float* __restrict__ w) {
    extern __shared__ __align__(16) float sm[];
    float* xs = sm;
    float* ws = sm + 2 * G1_XS;
    const uint32_t xs_u = smem_u32(xs), ws_u = smem_u32(ws);

    const int b = blockIdx.y, n0 = blockIdx.x * 128;
    const int t = threadIdx.x, lane = t & 31, wid = t >> 5;
    const int wm = (wid & 1) * 64, wn = (wid >> 1) * 32;
    const int q = lane >> 2, r = lane & 3;

    const int xrow = t >> 5, xcol = t & 31;
    const int wrow = t >> 3, wcol = t & 7;

    float acc[4][4][4] = {};

    auto load_chunk = [&](int ch, int bi) {
        const int d0 = ch * 32;
        uint32_t xd = xs_u + bi * G1_XS * 4;
        const float* xg = x + ((size_t)(b * ND + d0 + xrow)) * NN + n0 + xcol * 4;
        #pragma unroll
        for (int i = 0; i < 8; i++)
            CPA16(xd + (xrow + i * 4) * (XS1 * 4) + xcol * 16,
                  xg + (size_t)i * 4 * NN);
        uint32_t wd = ws_u + bi * G1_WS * 4;
        const float* wg = w + (size_t)wrow * ND + d0 + wcol * 4;
        #pragma unroll
        for (int i = 0; i < 4; i++)
            CPA16(wd + (wrow + i * 16) * (WS1 * 4) + wcol * 16,
                  wg + (size_t)i * 16 * ND);
        CPA_COMMIT();
    };

    load_chunk(0, 0);
    for (int ch = 0; ch < 16; ch++) {
        if (ch + 1 < 16) { load_chunk(ch + 1, (ch + 1) & 1); CPA_WAIT1(); }
        else CPA_WAIT0();
        __syncthreads();
        const float* xc = xs + (ch & 1) * G1_XS;
        const float* wc = ws + (ch & 1) * G1_WS;
        #pragma unroll
        for (int kk = 0; kk < 32; kk += 8) {
            uint32_t af[4][4], bf[4][2];
            #pragma unroll
            for (int mt = 0; mt < 4; mt++) {
                int m = wm + mt * 16 + q;
                af[mt][0] = F2U(xc[(kk + r) * XS1 + m]);
                af[mt][1] = F2U(xc[(kk + r) * XS1 + m + 8]);
                af[mt][2] = F2U(xc[(kk + r + 4) * XS1 + m]);
                af[mt][3] = F2U(xc[(kk + r + 4) * XS1 + m + 8]);
            }
            #pragma unroll
            for (int nt = 0; nt < 4; nt++) {
                int n = wn + nt * 8 + q;
                bf[nt][0] = F2U(wc[n * WS1 + kk + r]);
                bf[nt][1] = F2U(wc[n * WS1 + kk + r + 4]);
            }
            #pragma unroll
            for (int mt = 0; mt < 4; mt++)
                #pragma unroll
                for (int nt = 0; nt < 4; nt++)
                    mma8(acc[mt][nt], af[mt], bf[nt]);
        }
        __syncthreads();
    }

    float* fb = g_feat + (size_t)b * NK * NN + n0;
    #pragma unroll
    for (int mt = 0; mt < 4; mt++) {
        int m = wm + mt * 16 + q;
        #pragma unroll
        for (int nt = 0; nt < 4; nt++) {
            int kcl = wn + nt * 8 + 2 * r;
            fb[(size_t)kcl * NN + m]           = acc[mt][nt][0];
            fb[(size_t)(kcl + 1) * NN + m]     = acc[mt][nt][1];
            fb[(size_t)kcl * NN + m + 8]       = acc[mt][nt][2];
            fb[(size_t)(kcl + 1) * NN + m + 8] = acc[mt][nt][3];
        }
    }
}

// ---------------------------------------------------------------------------
// Softmax over H only: per (b,k,w) column of 32 values at stride 32. In-place.
// ---------------------------------------------------------------------------
__global__ void k_softmax() {
    const int bk = blockIdx.x * 8 + (threadIdx.x >> 5);
    const int t = threadIdx.x & 31;
    float* p = g_feat + (size_t)bk * NN + t;
    float v[32];
    float m = -1e30f;
    #pragma unroll
    for (int h = 0; h < 32; h++) { v[h] = p[h * 32]; m = fmaxf(m, v[h]); }
    float s = 0.f;
    #pragma unroll
    for (int h = 0; h < 32; h++) { v[h] = __expf(v[h] - m); s += v[h]; }
    const float inv = 1.f / s;
    #pragma unroll
    for (int h = 0; h < 32; h++) p[h * 32] = v[h] * inv;
}

// ---------------------------------------------------------------------------
// GEMM2: V[b,kcl,d] = sum_n a[b,kcl,n] x[b,d,n] - 32*c[kcl,d]
// CTA 128(d=M) x 64(kcl=N), K=1024 in 32 chunks of 32.
// Epilogue: -32c, L2-normalize over kcl per (d,b), coalesced store g_V[b][d][k].
// (sum_n a == 32 exactly: softmax columns each sum to 1, W=32 of them.)
// ---------------------------------------------------------------------------
#define XS2 36
#define AS2 36
#define G2_XS (128 * XS2)
#define G2_AS (64 * AS2)
#define G2_SMEM ((2 * G2_XS + 2 * G2_AS) * 4)
#define VS2 65

__global__ __launch_bounds__(128) void k_gemm2(const float* __restrict__ x,
                                               const float* __restrict__ cc) {
    extern __shared__ __align__(16) float sm[];
    float* xs = sm;
    float* as = sm + 2 * G2_XS;
    const uint32_t xs_u = smem_u32(xs), as_u = smem_u32(as);

    const int b = blockIdx.y, d0 = blockIdx.x * 128;
    const int t = threadIdx.x, lane = t & 31, wid = t >> 5;
    const int wm = (wid & 1) * 64, wn = (wid >> 1) * 32;
    const int q = lane >> 2, r = lane & 3;

    const int xrow = t >> 3, xcol = t & 7;

    float acc[4][4][4] = {};

    auto load_chunk = [&](int ch, int bi) {
        const int n0 = ch * 32;
        uint32_t xd = xs_u + bi * G2_XS * 4;
        const float* xg = x + ((size_t)(b * ND + d0 + xrow)) * NN + n0 + xcol * 4;
        #pragma unroll
        for (int i = 0; i < 8; i++)
            CPA16(xd + (xrow + i * 16) * (XS2 * 4) + xcol * 16,
                  xg + (size_t)i * 16 * NN);
        uint32_t ad = as_u + bi * G2_AS * 4;
        const float* ag = g_feat + ((size_t)(b * NK + xrow)) * NN + n0 + xcol * 4;
        #pragma unroll
        for (int i = 0; i < 4; i++)
            CPA16(ad + (xrow + i * 16) * (AS2 * 4) + xcol * 16,
                  ag + (size_t)i * 16 * NN);
        CPA_COMMIT();
    };

    load_chunk(0, 0);
    for (int ch = 0; ch < 32; ch++) {
        if (ch + 1 < 32) { load_chunk(ch + 1, (ch + 1) & 1); CPA_WAIT1(); }
        else CPA_WAIT0();
        __syncthreads();
        const float* xc = xs + (ch & 1) * G2_XS;
        const float* ac = as + (ch & 1) * G2_AS;
        #pragma unroll
        for (int kk = 0; kk < 32; kk += 8) {
            uint32_t af[4][4], bf[4][2];
            #pragma unroll
            for (int mt = 0; mt < 4; mt++) {
                int m = wm + mt * 16 + q;
                af[mt][0] = F2U(xc[m * XS2 + kk + r]);
                af[mt][1] = F2U(xc[(m + 8) * XS2 + kk + r]);
                af[mt][2] = F2U(xc[m * XS2 + kk + r + 4]);
                af[mt][3] = F2U(xc[(m + 8) * XS2 + kk + r + 4]);
            }
            #pragma unroll
            for (int nt = 0; nt < 4; nt++) {
                int n = wn + nt * 8 + q;
                bf[nt][0] = F2U(ac[n * AS2 + kk + r]);
                bf[nt][1] = F2U(ac[n * AS2 + kk + r + 4]);
            }
            #pragma unroll
            for (int mt = 0; mt < 4; mt++)
                #pragma unroll
                for (int nt = 0; nt < 4; nt++)
                    mma8(acc[mt][nt], af[mt], bf[nt]);
        }
        __syncthreads();
    }

    // stage raw V into smem, stride 65 (conflict-free column reads)
    float* Vs = sm;
    #pragma unroll
    for (int mt = 0; mt < 4; mt++) {
        int m = wm + mt * 16 + q;
        #pragma unroll
        for (int nt = 0; nt < 4; nt++) {
            int kcl = wn + nt * 8 + 2 * r;
            Vs[m * VS2 + kcl]           = acc[mt][nt][0];
            Vs[m * VS2 + kcl + 1]       = acc[mt][nt][1];
            Vs[(m + 8) * VS2 + kcl]     = acc[mt][nt][2];
            Vs[(m + 8) * VS2 + kcl + 1] = acc[mt][nt][3];
        }
    }
    __syncthreads();

    // per d (=t): subtract 32c, L2-normalize over kcl, coalesced store g_V[b][d][k]
    const float* crow = cc + d0 + t;
    float ss = 0.f;
    #pragma unroll
    for (int k = 0; k < NK; k++) {
        float v = Vs[t * VS2 + k] - 32.0f * crow[(size_t)k * ND];
        ss = fmaf(v, v, ss);
    }
    const float inv = 1.f / fmaxf(sqrtf(ss), 1e-12f);
    float* vp = g_V + ((size_t)(b * ND + d0 + t)) * NK;
    #pragma unroll
    for (int k = 0; k < NK; k += 4) {
        float4 o;
        o.x = (Vs[t * VS2 + k]     - 32.0f * crow[(size_t)(k)     * ND]) * inv;
        o.y = (Vs[t * VS2 + k + 1] - 32.0f * crow[(size_t)(k + 1) * ND]) * inv;
        o.z = (Vs[t * VS2 + k + 2] - 32.0f * crow[(size_t)(k + 2) * ND]) * inv;
        o.w = (Vs[t * VS2 + k + 3] - 32.0f * crow[(size_t)(k + 3) * ND]) * inv;
        *(float4*)(vp + k) = o;
    }
}

// ---------------------------------------------------------------------------
// Transpose g_V[b][d][k] -> out[d][k][b]. One CTA per d; both sides coalesced.
// ---------------------------------------------------------------------------
__global__ __launch_bounds__(512) void k_transpose(float* __restrict__ out) {
    __shared__ float tl[64][65];
    const int d = blockIdx.x;
    const int t = threadIdx.x;
    const int k = t & 63, bq = t >> 6;    // read: contiguous k per b
    #pragma unroll
    for (int i = 0; i < 8; i++) {
        int b = bq * 8 + i;
        tl[b][k] = g_V[((size_t)b * ND + d) * NK + k];
    }
    __syncthreads();
    const int b2 = t & 63, kq = t >> 6;   // write: contiguous b per k
    #pragma unroll
    for (int i = 0; i < 8; i++) {
        int kk = kq * 8 + i;
        out[((size_t)d * NK + kk) * NB + b2] = tl[b2][kk];
    }
}

// ---------------------------------------------------------------------------
extern "C" void kernel_launch(void* const* d_in, const int* in_sizes, int n_in,
                              void* d_out, int out_size) {
    const float* x = (const float*)d_in[0];  // (B,D,H,W)
    const float* w = (const float*)d_in[1];  // (K,D)
    const float* c = (const float*)d_in[2];  // (K,D)
    float* out = (float*)d_out;              // (D,K,B)

    cudaFuncSetAttribute(k_gemm1, cudaFuncAttributeMaxDynamicSharedMemorySize, G1_SMEM);
    cudaFuncSetAttribute(k_gemm2, cudaFuncAttributeMaxDynamicSharedMemorySize, G2_SMEM);

    k_gemm1<<<dim3(NN / 128, NB), 128, G1_SMEM>>>(x, w);
    k_softmax<<<NB * NK / 8, 256>>>();
    k_gemm2<<<dim3(ND / 128, NB), 128, G2_SMEM>>>(x, c);
    k_transpose<<<ND, 512>>>(out);
}